// round 3
// baseline (speedup 1.0000x reference)
#include <cuda_runtime.h>

#define Bq 256
#define Tq 64
#define Nq 128
#define Hq 512
#define Kq 640   // Nq + Hq
#define Gq 2048  // 4*Hq

// ---------------- device scratch (no allocs allowed) ----------------
__device__ __align__(16) float g_z2[Bq * Nq * Tq];   // (B,N,T) loop-invariant attention term
__device__ __align__(16) float g_Wp[Kq * Gq];        // combined [W_ih; W_hh], cols permuted j' = h*4+g
__device__ __align__(16) float g_bias[Gq];           // (b_ih+b_hh) permuted
__device__ __align__(16) float g_A[Bq * Kq];         // activation rows: [wx(128) | h(512)]
__device__ __align__(16) float g_C[Bq * Hq];         // cell state

__device__ __forceinline__ float tanh_approx(float x) {
    float y;
    asm("tanh.approx.f32 %0, %1;" : "=f"(y) : "f"(x));
    return y;
}

// ---------------- prep: weights, bias, zero state ----------------
__global__ __launch_bounds__(256) void prep_weights(const float* __restrict__ Wih,
                                                    const float* __restrict__ Whh,
                                                    const float* __restrict__ bih,
                                                    const float* __restrict__ bhh) {
    int i = blockIdx.x * blockDim.x + threadIdx.x;
    int stride = gridDim.x * blockDim.x;
    for (int idx = i; idx < Kq * Gq; idx += stride) {
        int k = idx / Gq, jp = idx - k * Gq;
        int h = jp >> 2, g = jp & 3;
        int j = g * Hq + h;  // source column in torch gate order i,f,g,o
        g_Wp[idx] = (k < Nq) ? Wih[j * Nq + k] : Whh[j * Hq + (k - Nq)];
    }
    for (int idx = i; idx < Gq; idx += stride) {
        int h = idx >> 2, g = idx & 3;
        int j = g * Hq + h;
        g_bias[idx] = bih[j] + bhh[j];
    }
    for (int idx = i; idx < Bq * Kq; idx += stride) g_A[idx] = 0.f;
    for (int idx = i; idx < Bq * Hq; idx += stride) g_C[idx] = 0.f;
}

// ---------------- prep: z2[b,n,s] = sum_t dx[b,t,n]*W_a2[s,t] + b_a2[s] ----------------
__global__ __launch_bounds__(256) void prep_z2(const float* __restrict__ dx,
                                               const float* __restrict__ Wa2,
                                               const float* __restrict__ ba2) {
    __shared__ float sdx[Tq * Nq];  // [t][n], 32KB
    int b = blockIdx.x, tid = threadIdx.x;
    const float* dxb = dx + b * Tq * Nq;
    for (int i = tid; i < Tq * Nq; i += 256) sdx[i] = dxb[i];
    __syncthreads();
    for (int o = tid; o < Nq * Tq; o += 256) {
        int s = o & 63, n = o >> 6;
        float acc = 0.f;
#pragma unroll 8
        for (int t = 0; t < Tq; t++) acc += sdx[t * Nq + n] * __ldg(&Wa2[s * Tq + t]);
        g_z2[(b * Nq + n) * Tq + s] = acc + ba2[s];
    }
}

// ---------------- per step: z1 + attention + softmax + wx, one block per batch ----------------
__global__ __launch_bounds__(256) void step_z1attn(const float* __restrict__ Wa1,
                                                   const float* __restrict__ ba1,
                                                   const float* __restrict__ Wa3,
                                                   const float* __restrict__ ba3,
                                                   const float* __restrict__ dx, int t) {
    __shared__ float hs[2 * Hq];    // [h | c], 4KB
    __shared__ float z1s[Tq];
    __shared__ float wa3s[Tq];
    __shared__ float red[8];
    const int b = blockIdx.x, tid = threadIdx.x;

    // load h, c of this batch
    for (int i = tid; i < Hq; i += 256) hs[i] = g_A[b * Kq + Nq + i];
    for (int i = tid; i < Hq; i += 256) hs[Hq + i] = g_C[b * Hq + i];
    if (tid < Tq) wa3s[tid] = Wa3[tid];
    __syncthreads();

    // z1[s] = hs . Wa1[s,:], 4 threads per s (each 256 elems), shfl reduce
    {
        const int s = tid >> 2, part = tid & 3;  // s in [0,64)
        const float* wrow = Wa1 + s * (2 * Hq) + part * 256;
        const float* hp = hs + part * 256;
        float acc = 0.f;
#pragma unroll 8
        for (int k = 0; k < 256; k += 4) {
            float4 w = *(const float4*)(wrow + k);
            acc += hp[k] * w.x + hp[k + 1] * w.y + hp[k + 2] * w.z + hp[k + 3] * w.w;
        }
        acc += __shfl_xor_sync(0xffffffff, acc, 1);
        acc += __shfl_xor_sync(0xffffffff, acc, 2);
        if (part == 0) z1s[s] = acc + ba1[s];
    }
    __syncthreads();

    // e[n] = sum_s tanh(z1[s] + z2[b,n,s]) * Wa3[s] + ba3; first 128 threads (n = tid)
    float e = 0.f;
    if (tid < Nq) {
        const float4* z2r = (const float4*)(g_z2 + (b * Nq + tid) * Tq);
        e = ba3[0];
#pragma unroll
        for (int s4 = 0; s4 < Tq / 4; s4++) {
            float4 z = z2r[s4];
            int s = s4 * 4;
            e += tanh_approx(z1s[s + 0] + z.x) * wa3s[s + 0];
            e += tanh_approx(z1s[s + 1] + z.y) * wa3s[s + 1];
            e += tanh_approx(z1s[s + 2] + z.z) * wa3s[s + 2];
            e += tanh_approx(z1s[s + 3] + z.w) * wa3s[s + 3];
        }
    }
    // softmax over n in [0,128): reduce across 4 active warps
    float m = e;
    for (int o = 16; o > 0; o >>= 1) m = fmaxf(m, __shfl_xor_sync(0xffffffff, m, o));
    if ((tid & 31) == 0) red[tid >> 5] = (tid < Nq) ? m : -1e30f;
    __syncthreads();
    m = fmaxf(fmaxf(red[0], red[1]), fmaxf(red[2], red[3]));
    float p = (tid < Nq) ? __expf(e - m) : 0.f;
    float sum = p;
    for (int o = 16; o > 0; o >>= 1) sum += __shfl_xor_sync(0xffffffff, sum, o);
    __syncthreads();
    if ((tid & 31) == 0) red[tid >> 5] = sum;
    __syncthreads();
    sum = red[0] + red[1] + red[2] + red[3];
    if (tid < Nq) {
        float w = p / sum;
        float x = dx[(b * Tq + t) * Nq + tid];
        g_A[b * Kq + tid] = w * x;
    }
}

// ---------------- per step: gates GEMM + fused LSTM update ----------------
// grid (8,16): 32-batch x 32-h tile (128 gate cols). 256 threads, each owns 4 batches x 1 h.
__global__ __launch_bounds__(256) void step_gemm(float* __restrict__ out, int t) {
    __shared__ float sA[32 * 33];   // [k][row], padded
    __shared__ float4 sW[32 * 32];  // [k][col-quad]
    const int tid = threadIdx.x;
    const int bm = blockIdx.x * 32;
    const int hb = blockIdx.y * 32;
    const int wid = tid >> 5, lane = tid & 31;
    const int rr = tid >> 3, kq = tid & 7;

    float4 acc[4];
#pragma unroll
    for (int u = 0; u < 4; u++) acc[u] = make_float4(0.f, 0.f, 0.f, 0.f);

    const float* Arow = g_A + (bm + rr) * Kq + kq * 4;
    float4 ra, rw[4];
    ra = *(const float4*)(Arow);
#pragma unroll
    for (int l = 0; l < 4; l++) {
        int idx = tid + l * 256;
        int kk = idx >> 5, cs = idx & 31;
        rw[l] = *(const float4*)(g_Wp + kk * Gq + hb * 4 + cs * 4);
    }
    const int NCH = Kq / 32;  // 20
    for (int c = 0; c < NCH; c++) {
        sA[(kq * 4 + 0) * 33 + rr] = ra.x;
        sA[(kq * 4 + 1) * 33 + rr] = ra.y;
        sA[(kq * 4 + 2) * 33 + rr] = ra.z;
        sA[(kq * 4 + 3) * 33 + rr] = ra.w;
#pragma unroll
        for (int l = 0; l < 4; l++) sW[tid + l * 256] = rw[l];
        __syncthreads();
        if (c + 1 < NCH) {
            int k0 = (c + 1) * 32;
            ra = *(const float4*)(Arow + k0);
#pragma unroll
            for (int l = 0; l < 4; l++) {
                int idx = tid + l * 256;
                int kk = idx >> 5, cs = idx & 31;
                rw[l] = *(const float4*)(g_Wp + (k0 + kk) * Gq + hb * 4 + cs * 4);
            }
        }
#pragma unroll
        for (int k = 0; k < 32; k++) {
            float4 wv = sW[k * 32 + lane];
#pragma unroll
            for (int u = 0; u < 4; u++) {
                float a = sA[k * 33 + (wid << 2) + u];
                acc[u].x = fmaf(a, wv.x, acc[u].x);
                acc[u].y = fmaf(a, wv.y, acc[u].y);
                acc[u].z = fmaf(a, wv.z, acc[u].z);
                acc[u].w = fmaf(a, wv.w, acc[u].w);
            }
        }
        __syncthreads();
    }
    // fused LSTM pointwise update
    const int h = hb + lane;
    float4 bias = *(const float4*)(g_bias + h * 4);
#pragma unroll
    for (int u = 0; u < 4; u++) {
        int b = bm + (wid << 2) + u;
        float gi = acc[u].x + bias.x;
        float gf = acc[u].y + bias.y;
        float gg = acc[u].z + bias.z;
        float go = acc[u].w + bias.w;
        float co = g_C[b * Hq + h];
        float si = 1.f / (1.f + __expf(-gi));
        float sf = 1.f / (1.f + __expf(-gf));
        float so = 1.f / (1.f + __expf(-go));
        float cn = sf * co + si * tanhf(gg);
        float hn = so * tanhf(cn);
        g_C[b * Hq + h] = cn;
        g_A[b * Kq + Nq + h] = hn;
        out[(b * Tq + t) * Hq + h] = hn;
    }
}

extern "C" void kernel_launch(void* const* d_in, const int* in_sizes, int n_in,
                              void* d_out, int out_size) {
    const float* dx  = (const float*)d_in[0];
    const float* Wa1 = (const float*)d_in[1];
    const float* ba1 = (const float*)d_in[2];
    const float* Wa2 = (const float*)d_in[3];
    const float* ba2 = (const float*)d_in[4];
    const float* Wa3 = (const float*)d_in[5];
    const float* ba3 = (const float*)d_in[6];
    const float* Wih = (const float*)d_in[7];
    const float* Whh = (const float*)d_in[8];
    const float* bih = (const float*)d_in[9];
    const float* bhh = (const float*)d_in[10];
    float* out = (float*)d_out;

    prep_weights<<<512, 256>>>(Wih, Whh, bih, bhh);
    prep_z2<<<Bq, 256>>>(dx, Wa2, ba2);
    for (int t = 0; t < Tq; t++) {
        step_z1attn<<<Bq, 256>>>(Wa1, ba1, Wa3, ba3, dx, t);
        dim3 g2(8, 16);
        step_gemm<<<g2, 256>>>(out, t);
    }
}